// round 10
// baseline (speedup 1.0000x reference)
#include <cuda_runtime.h>

// Shapes (fixed)
#define B_ 32
#define P_ 196
#define D_ 512
#define H_ 8
#define U_ 4
#define C_ 500

#define KNOWN_ELEMS (B_ * C_ * (H_ + 3) * D_)   // 90,112,000
#define UNK_ELEMS   (B_ * (U_ + 3) * D_)        // 114,688
#define NUNITS      (B_ * C_)                    // 16000

// Scratch (device globals — no allocation allowed)
__device__ float g_dom[B_ * D_];
__device__ float g_sem[B_ * H_ * D_];
__device__ float g_scores[B_ * P_ * H_];

// ---------------------------------------------------------------------------
// Kernel 1: scores[b,p,h] = patch[b,p,:] . query[h,:]
// grid 784 x 256 thr, warp per (b,p), float4 MLP=4.
// ---------------------------------------------------------------------------
__global__ __launch_bounds__(256) void k_scores(const float* __restrict__ patch,
                                                const float* __restrict__ query) {
    __shared__ float4 q_sh[H_ * 128];   // 16 KB
    const int tid = threadIdx.x;
    for (int i = tid; i < H_ * 128; i += 256)
        q_sh[i] = ((const float4*)query)[i];
    __syncthreads();

    const int warp = tid >> 5, lane = tid & 31;
    const int gw = blockIdx.x * 8 + warp;     // 0..6271
    const int b = gw / P_;
    const int p = gw - b * P_;
    const float4* row = (const float4*)(patch + ((size_t)b * P_ + p) * D_);

    float acc[H_];
#pragma unroll
    for (int h = 0; h < H_; h++) acc[h] = 0.f;
#pragma unroll
    for (int i = 0; i < 4; i++) {
        float4 x = row[lane + i * 32];
#pragma unroll
        for (int h = 0; h < H_; h++) {
            float4 q = q_sh[h * 128 + lane + i * 32];
            acc[h] += x.x * q.x + x.y * q.y + x.z * q.z + x.w * q.w;
        }
    }
#pragma unroll
    for (int h = 0; h < H_; h++) {
#pragma unroll
        for (int o = 16; o; o >>= 1)
            acc[h] += __shfl_xor_sync(0xffffffffu, acc[h], o);
    }
    if (lane == 0) {
        float* s = g_scores + ((size_t)b * P_ + p) * H_;
#pragma unroll
        for (int h = 0; h < H_; h++) s[h] = acc[h];
    }
}

// ---------------------------------------------------------------------------
// Kernel 2: softmax over P + weighted pooling.
// grid (B_, 4 d-tiles), block 512 = 128 d x 4 p-quarters (49 p each).
// ---------------------------------------------------------------------------
__global__ __launch_bounds__(512) void k_pool(const float* __restrict__ patch,
                                              float* __restrict__ sem_out) {
    __shared__ float w_sh[P_ * H_];         // 1568
    __shared__ float mmax[H_], inv_s[H_];
    __shared__ float psum[3 * 128 * H_];    // partials from p-quarters 1..3

    const int b  = blockIdx.x;
    const int dt = blockIdx.y;
    const int tid = threadIdx.x;
    const int warp = tid >> 5, lane = tid & 31;

    const float* sc = g_scores + (size_t)b * P_ * H_;
    for (int i = tid; i < P_ * H_; i += 512) w_sh[i] = sc[i];
    __syncthreads();

    if (warp < H_) {          // 8 warps compute 8 heads' stats
        const int h = warp;
        float m = -1e30f;
        for (int p = lane; p < P_; p += 32) m = fmaxf(m, w_sh[p * H_ + h]);
#pragma unroll
        for (int o = 16; o; o >>= 1) m = fmaxf(m, __shfl_xor_sync(0xffffffffu, m, o));
        float s = 0.f;
        for (int p = lane; p < P_; p += 32) s += __expf(w_sh[p * H_ + h] - m);
#pragma unroll
        for (int o = 16; o; o >>= 1) s += __shfl_xor_sync(0xffffffffu, s, o);
        if (lane == 0) { mmax[h] = m; inv_s[h] = 1.f / s; }
    }
    __syncthreads();
    for (int i = tid; i < P_ * H_; i += 512) {
        int h = i & (H_ - 1);
        w_sh[i] = __expf(w_sh[i] - mmax[h]) * inv_s[h];
    }
    __syncthreads();

    const int d_local = tid & 127;
    const int pq      = tid >> 7;          // 0..3
    const int d       = dt * 128 + d_local;
    const int p0      = pq * 49;
    const float* pb = patch + ((size_t)b * P_ + p0) * D_ + d;

    float acc[H_];
#pragma unroll
    for (int h = 0; h < H_; h++) acc[h] = 0.f;
#pragma unroll
    for (int r = 0; r < 7; r++) {
        float x[7];
#pragma unroll
        for (int q = 0; q < 7; q++) x[q] = pb[(r * 7 + q) * D_];
#pragma unroll
        for (int q = 0; q < 7; q++) {
            const float* wr = w_sh + (p0 + r * 7 + q) * H_;
#pragma unroll
            for (int h = 0; h < H_; h++) acc[h] = fmaf(wr[h], x[q], acc[h]);
        }
    }
    if (pq > 0) {
#pragma unroll
        for (int h = 0; h < H_; h++)
            psum[((pq - 1) * 128 + d_local) * H_ + h] = acc[h];
    }
    __syncthreads();
    if (pq == 0) {
#pragma unroll
        for (int h = 0; h < H_; h++) {
            float v = acc[h]
                    + psum[(0 * 128 + d_local) * H_ + h]
                    + psum[(1 * 128 + d_local) * H_ + h]
                    + psum[(2 * 128 + d_local) * H_ + h];
            sem_out[((size_t)b * H_ + h) * D_ + d] = v;
        }
    }
}

// ---------------------------------------------------------------------------
// Kernel 3: projections — REWORKED.
// grid = 9 (8 heads + dom) x 16 e-tiles(32) x 2 b-halves(16) = 288 blocks.
// Block 256 thr computes 32e x 16b tile; k-chunks of 64, double-buffered
// register prefetch; W rows padded to 68 floats (16B-aligned LDS.128).
// ---------------------------------------------------------------------------
#define NCHUNK 8                 // 512 / 64
__global__ __launch_bounds__(256) void k_proj(const float* __restrict__ sem_tok,
                                              const float* __restrict__ semW,
                                              const float* __restrict__ semb,
                                              const float* __restrict__ gf,
                                              const float* __restrict__ domW,
                                              const float* __restrict__ domb) {
    __shared__ float4 Tsh[2][16 * 16];      // 16 b-rows x 16 float4 per buf
    __shared__ float  Wsh[2][32 * 68];      // 32 e-rows x 68 (17 float4) per buf

    const int tid = threadIdx.x;
    const int bx  = blockIdx.x;
    const int y   = bx >> 5;               // 0..8 (8 = domain)
    const int r   = bx & 31;
    const int e0  = (r >> 1) * 32;
    const int b0  = (r & 1) * 16;
    const bool dom = (y == 8);

    const float* Tbase   = dom ? gf : (sem_tok + (size_t)y * D_);
    const size_t Tstride = dom ? (size_t)D_ : (size_t)H_ * D_;
    const float* Wbase   = dom ? (domW + (size_t)e0 * D_)
                               : (semW + ((size_t)y * D_ + e0) * D_);

    const int lrow = tid >> 4;             // 0..15
    const int lkq  = tid & 15;             // 0..15 (float4 within chunk)
    const float4* Tg  = (const float4*)(Tbase + (size_t)(b0 + lrow) * Tstride);
    const float4* Wg0 = (const float4*)(Wbase + (size_t)lrow * D_);
    const float4* Wg1 = (const float4*)(Wbase + (size_t)(lrow + 16) * D_);

    // preload chunk 0
    float4 tv  = Tg[lkq];
    float4 wv0 = Wg0[lkq];
    float4 wv1 = Wg1[lkq];
    Tsh[0][lrow * 16 + lkq] = tv;
    ((float4*)(Wsh[0] + lrow * 68))[lkq]        = wv0;
    ((float4*)(Wsh[0] + (lrow + 16) * 68))[lkq] = wv1;
    __syncthreads();

    const int e_local = tid & 31;          // 0..31
    const int bq      = tid >> 5;          // 0..7 -> b rows bq, bq+8
    float acc0 = 0.f, acc1 = 0.f;

    for (int c = 0; c < NCHUNK; c++) {
        const int cur = c & 1;
        if (c + 1 < NCHUNK) {              // prefetch next chunk into regs
            const int o4 = (c + 1) * 16;
            tv  = Tg[o4 + lkq];
            wv0 = Wg0[o4 + lkq];
            wv1 = Wg1[o4 + lkq];
        }
        const float4* wrow = (const float4*)(Wsh[cur] + e_local * 68);
        const float4* t0   = &Tsh[cur][bq * 16];
        const float4* t1   = &Tsh[cur][(bq + 8) * 16];
#pragma unroll
        for (int k4 = 0; k4 < 16; k4++) {
            const float4 w = wrow[k4];
            const float4 a = t0[k4];
            const float4 b = t1[k4];
            acc0 = fmaf(w.x, a.x, acc0); acc0 = fmaf(w.y, a.y, acc0);
            acc0 = fmaf(w.z, a.z, acc0); acc0 = fmaf(w.w, a.w, acc0);
            acc1 = fmaf(w.x, b.x, acc1); acc1 = fmaf(w.y, b.y, acc1);
            acc1 = fmaf(w.z, b.z, acc1); acc1 = fmaf(w.w, b.w, acc1);
        }
        __syncthreads();
        if (c + 1 < NCHUNK) {
            const int nxt = 1 - cur;
            Tsh[nxt][lrow * 16 + lkq] = tv;
            ((float4*)(Wsh[nxt] + lrow * 68))[lkq]        = wv0;
            ((float4*)(Wsh[nxt] + (lrow + 16) * 68))[lkq] = wv1;
            __syncthreads();
        }
    }

    const int e  = e0 + e_local;
    const int ba = b0 + bq;
    const int bb = b0 + bq + 8;
    if (dom) {
        const float bv = domb[e];
        g_dom[ba * D_ + e] = acc0 + bv;
        g_dom[bb * D_ + e] = acc1 + bv;
    } else {
        const float bv = semb[y * D_ + e];
        g_sem[((size_t)ba * H_ + y) * D_ + e] = acc0 + bv;
        g_sem[((size_t)bb * H_ + y) * D_ + e] = acc1 + bv;
    }
}

// ---------------------------------------------------------------------------
// Kernel S (side stream): data-independent tokens — prefix(0) + suffix(10)
// of every known unit. 65 MB streaming stores, overlapped with compute.
// ---------------------------------------------------------------------------
__global__ __launch_bounds__(256) void k_static(const float4* __restrict__ pre,
                                                const float4* __restrict__ suf,
                                                float4* __restrict__ out) {
    const int u = blockIdx.x;
    const int c = u % C_;
    const int half = threadIdx.x >> 7, j = threadIdx.x & 127;
    const float4 v = half ? suf[(size_t)c * 128 + j] : pre[(size_t)c * 128 + j];
    __stcs(&out[(size_t)u * (11 * 128) + half * (10 * 128) + j], v);
}

// ---------------------------------------------------------------------------
// Kernel 4: dependent tokens (1..9) of known units + full unknown prompts.
// 295 MB streaming stores at max occupancy.
// ---------------------------------------------------------------------------
__global__ __launch_bounds__(256) void k_dep(const float4* __restrict__ upre,
                                             const float4* __restrict__ usem,
                                             const float4* __restrict__ usuf,
                                             float4* __restrict__ out,
                                             float4* __restrict__ unk_out) {
    const int u = blockIdx.x;
    if (u < NUNITS) {
        const int b = u / C_;
        float4* o = out + (size_t)u * (11 * 128) + 128;   // tokens 1..9
        const float4* dm = ((const float4*)g_dom) + b * 128;
        const float4* sm = ((const float4*)g_sem) + (size_t)b * H_ * 128;
        for (int i = threadIdx.x; i < 9 * 128; i += 256) {
            const int tk = i >> 7, j = i & 127;
            const float4 v = (tk == 0) ? dm[j] : sm[(tk - 1) * 128 + j];
            __stcs(&o[i], v);
        }
    } else {
        const int b = u - NUNITS;
        float4* o = unk_out + (size_t)b * 7 * 128;
        const float4* dm = ((const float4*)g_dom) + b * 128;
        for (int i = threadIdx.x; i < 7 * 128; i += 256) {
            const int tk = i >> 7, j = i & 127;
            float4 v;
            if (tk == 0)      v = upre[j];
            else if (tk == 1) v = dm[j];
            else if (tk < 6)  v = usem[(tk - 2) * 128 + j];
            else              v = usuf[j];
            __stcs(&o[i], v);
        }
    }
}

// ---------------------------------------------------------------------------
extern "C" void kernel_launch(void* const* d_in, const int* in_sizes, int n_in,
                              void* d_out, int out_size) {
    const float* patch = (const float*)d_in[0];
    const float* gf    = (const float*)d_in[1];
    const float* query = (const float*)d_in[2];
    const float* domW  = (const float*)d_in[3];
    const float* domb  = (const float*)d_in[4];
    const float* semW  = (const float*)d_in[5];
    const float* semb  = (const float*)d_in[6];
    const float* usem  = (const float*)d_in[7];
    const float* pre   = (const float*)d_in[8];
    const float* suf   = (const float*)d_in[9];
    const float* upre  = (const float*)d_in[10];
    const float* usuf  = (const float*)d_in[11];

    float* out     = (float*)d_out;
    float* unk_out = out + (size_t)KNOWN_ELEMS;
    float* sem_out = out + (size_t)KNOWN_ELEMS + UNK_ELEMS;

    static cudaStream_t s_side = nullptr;
    static cudaEvent_t evA = nullptr, evB = nullptr;
    if (s_side == nullptr) {
        cudaStreamCreateWithFlags(&s_side, cudaStreamNonBlocking);
        cudaEventCreateWithFlags(&evA, cudaEventDisableTiming);
        cudaEventCreateWithFlags(&evB, cudaEventDisableTiming);
    }

    // Fork: static writer on the side stream, concurrent with compute.
    cudaEventRecord(evA, 0);
    cudaStreamWaitEvent(s_side, evA, 0);
    k_static<<<NUNITS, 256, 0, s_side>>>((const float4*)pre, (const float4*)suf,
                                         (float4*)out);
    cudaEventRecord(evB, s_side);

    // Compute chain on the main (capture) stream.
    k_scores<<<(B_ * P_) / 8, 256>>>(patch, query);
    k_pool<<<dim3(B_, 4), 512>>>(patch, sem_out);
    k_proj<<<9 * 32, 256>>>(sem_out, semW, semb, gf, domW, domb);

    // Join, then the big dependent writer at full occupancy.
    cudaStreamWaitEvent(0, evB, 0);
    k_dep<<<NUNITS + B_, 256>>>((const float4*)upre, (const float4*)usem,
                                (const float4*)usuf,
                                (float4*)out, (float4*)unk_out);
}